// round 1
// baseline (speedup 1.0000x reference)
#include <cuda_runtime.h>
#include <math.h>

// ---------------- problem constants ----------------
constexpr int NB   = 32;     // batch
constexpr int NC   = 768;    // conv channels
constexpr int CIN0 = 80;     // mel channels
constexpr int T0   = 1024;
constexpr int T1   = 1022;
constexpr int T2   = 511;
constexpr int ND   = 64;     // code dim
constexpr int NM   = 512;    // codebook size
constexpr int NQ   = NB * T2;      // 16352 vectors
constexpr int NQE  = NQ * ND;      // 1046528 output elems for q_st
constexpr float BN_EPS = 1e-5f;

// ---------------- scratch (static device globals; no allocs) ----------------
__device__ float g_bufA[NB * NC * T1];          // 25.1M floats
__device__ float g_bufB[NB * NC * T1];
__device__ float g_w1T[CIN0 * 3 * NC];
__device__ float g_w2T[NC * 3 * NC];
__device__ float g_w3T[NC * 4 * NC];
__device__ float g_w4T[NC * 3 * NC];
__device__ float g_w5T[NC * 3 * NC];
__device__ float g_z[NQE];                       // z in [B, T', D]
__device__ float g_dist[NQ * NM];                // 8.37M floats
__device__ float g_bnInv[5 * NC];
__device__ float g_bnBeta[5 * NC];
__device__ float g_e2[NM];
__device__ int   g_counts[NM];
__device__ float g_loss[1];

// ---------------- tiny prep kernels ----------------
__global__ void zero_k() {
    int i = threadIdx.x;
    if (i < NM) g_counts[i] = 0;
    if (i == NM) g_loss[0] = 0.f;
}

__global__ void bnprep_k(const float* __restrict__ g, const float* __restrict__ b,
                         const float* __restrict__ m, const float* __restrict__ v) {
    int i = blockIdx.x * blockDim.x + threadIdx.x;
    if (i < 5 * NC) {
        float inv = g[i] * rsqrtf(v[i] + BN_EPS);
        g_bnInv[i]  = inv;
        g_bnBeta[i] = b[i] - m[i] * inv;
    }
}

// wT[kk * Cout + m] = w[m * KK + kk]
__global__ void transpose_w_k(const float* __restrict__ w, float* __restrict__ wT,
                              int Cout, int KK) {
    int i = blockIdx.x * blockDim.x + threadIdx.x;
    if (i < Cout * KK) {
        int m = i / KK, kk = i - m * KK;
        wT[kk * Cout + m] = w[i];
    }
}

__global__ void e2_k(const float* __restrict__ emb) {
    int e = blockIdx.x * blockDim.x + threadIdx.x;
    if (e < NM) {
        float s = 0.f;
        #pragma unroll
        for (int d = 0; d < ND; d++) { float t = emb[e * ND + d]; s += t * t; }
        g_e2[e] = s;
    }
}

// ---------------- conv1d + BN + ReLU as implicit-im2col GEMM ----------------
// out[(n*NC + m)*TOUT + t] = relu( BN( sum_{ci,k} x[n,ci,t*S+k-P] * w[m,ci,k] ) )
// wT is [KK, NC] row-major (KK = CIN*KW).
template<int KW, int STRIDE, int PAD, int CIN, int TIN, int TOUT>
__global__ __launch_bounds__(256)
void conv_bn_relu_k(const float* __restrict__ x, const float* __restrict__ wT,
                    const float* __restrict__ inv, const float* __restrict__ bet,
                    float* __restrict__ out)
{
    constexpr int KK    = CIN * KW;
    constexpr int NCOLS = NB * TOUT;
    __shared__ float As[16][64];
    __shared__ float Bs[16][64];

    const int tx = threadIdx.x, ty = threadIdx.y;
    const int tid = ty * 16 + tx;
    const int m0 = blockIdx.y * 64, n0 = blockIdx.x * 64;

    // B-load column (fixed per thread)
    const int colB  = tid & 63;
    const int kkB0  = tid >> 6;      // 0..3
    const int ncolB = n0 + colB;
    const int nB    = ncolB / TOUT;
    const int tB    = ncolB - nB * TOUT;
    const bool colValid = (ncolB < NCOLS);

    float acc[4][4] = {};

    for (int kt = 0; kt < KK; kt += 16) {
        #pragma unroll
        for (int j = 0; j < 4; j++) {          // A tile: [16][64] from wT (coalesced)
            int idx = tid + j * 256;
            int kkl = idx >> 6, ml = idx & 63;
            As[kkl][ml] = wT[(kt + kkl) * NC + m0 + ml];
        }
        #pragma unroll
        for (int j = 0; j < 4; j++) {          // B tile: implicit im2col
            int kk = kt + kkB0 + j * 4;
            int ci = kk / KW;
            int k  = kk - ci * KW;
            int tin = tB * STRIDE + k - PAD;
            float v = 0.f;
            if (colValid && tin >= 0 && tin < TIN)
                v = x[(nB * CIN + ci) * TIN + tin];
            Bs[kkB0 + j * 4][colB] = v;
        }
        __syncthreads();
        #pragma unroll
        for (int k = 0; k < 16; k++) {
            float4 a4 = *(const float4*)&As[k][ty * 4];
            float4 b4 = *(const float4*)&Bs[k][tx * 4];
            float av[4] = {a4.x, a4.y, a4.z, a4.w};
            float bv[4] = {b4.x, b4.y, b4.z, b4.w};
            #pragma unroll
            for (int i = 0; i < 4; i++)
                #pragma unroll
                for (int j = 0; j < 4; j++)
                    acc[i][j] = fmaf(av[i], bv[j], acc[i][j]);
        }
        __syncthreads();
    }

    #pragma unroll
    for (int i = 0; i < 4; i++) {
        int m = m0 + ty * 4 + i;
        float iv = inv[m], bb = bet[m];
        #pragma unroll
        for (int j = 0; j < 4; j++) {
            int ncol = n0 + tx * 4 + j;
            if (ncol < NCOLS) {
                int n = ncol / TOUT, t = ncol - n * TOUT;
                float v = acc[i][j] * iv + bb;
                out[(n * NC + m) * TOUT + t] = v > 0.f ? v : 0.f;
            }
        }
    }
}

// ---------------- 1x1 projection + bias + transpose to [B, T', D] ----------------
__global__ __launch_bounds__(256)
void conv6_k(const float* __restrict__ x, const float* __restrict__ w6,
             const float* __restrict__ b6, float* __restrict__ z)
{
    __shared__ float Xs[16][64];
    __shared__ float Ws[16][65];
    const int tx = threadIdx.x, ty = threadIdx.y;
    const int tid = ty * 16 + tx;
    const int t0 = blockIdx.x * 64;
    const int b  = blockIdx.y;

    float acc[4][4] = {};
    for (int c0 = 0; c0 < NC; c0 += 16) {
        #pragma unroll
        for (int j = 0; j < 4; j++) {
            int idx = tid + j * 256;
            int tl = idx & 63, kk = idx >> 6;
            int t = t0 + tl;
            Xs[kk][tl] = (t < T2) ? x[(b * NC + c0 + kk) * T2 + t] : 0.f;
        }
        #pragma unroll
        for (int j = 0; j < 4; j++) {
            int idx = tid + j * 256;
            int dl = idx & 63, kk = idx >> 6;
            Ws[kk][dl] = w6[dl * NC + c0 + kk];
        }
        __syncthreads();
        #pragma unroll
        for (int k = 0; k < 16; k++) {
            float a[4], w[4];
            #pragma unroll
            for (int i = 0; i < 4; i++) a[i] = Xs[k][ty * 4 + i];
            #pragma unroll
            for (int j = 0; j < 4; j++) w[j] = Ws[k][tx * 4 + j];
            #pragma unroll
            for (int i = 0; i < 4; i++)
                #pragma unroll
                for (int j = 0; j < 4; j++)
                    acc[i][j] = fmaf(a[i], w[j], acc[i][j]);
        }
        __syncthreads();
    }
    #pragma unroll
    for (int i = 0; i < 4; i++) {
        int t = t0 + ty * 4 + i;
        if (t < T2) {
            #pragma unroll
            for (int j = 0; j < 4; j++) {
                int d = tx * 4 + j;
                z[(b * T2 + t) * ND + d] = acc[i][j] + b6[d];
            }
        }
    }
}

// ---------------- VQ distance GEMM: dist[row][e] = ||e||^2 - 2 * z.e ----------------
__global__ __launch_bounds__(256)
void dist_k(const float* __restrict__ emb)
{
    __shared__ float zs[64][65];
    __shared__ float es[64][65];
    const int tx = threadIdx.x, ty = threadIdx.y;
    const int tid = ty * 16 + tx;
    const int row0 = blockIdx.x * 64;
    const int e0   = blockIdx.y * 64;

    #pragma unroll
    for (int j = 0; j < 16; j++) {
        int idx = tid + j * 256;        // 4096 elems
        int k = idx & 63, r = idx >> 6;
        zs[r][k] = (row0 + r < NQ) ? g_z[(row0 + r) * ND + k] : 0.f;
    }
    #pragma unroll
    for (int j = 0; j < 16; j++) {
        int idx = tid + j * 256;
        int k = idx & 63, e = idx >> 6;
        es[e][k] = emb[(e0 + e) * ND + k];
    }
    __syncthreads();

    float acc[4][4] = {};
    #pragma unroll
    for (int k = 0; k < 64; k++) {
        float a[4], b[4];
        #pragma unroll
        for (int i = 0; i < 4; i++) a[i] = zs[ty * 4 + i][k];
        #pragma unroll
        for (int j = 0; j < 4; j++) b[j] = es[tx * 4 + j][k];
        #pragma unroll
        for (int i = 0; i < 4; i++)
            #pragma unroll
            for (int j = 0; j < 4; j++)
                acc[i][j] = fmaf(a[i], b[j], acc[i][j]);
    }

    #pragma unroll
    for (int i = 0; i < 4; i++) {
        int row = row0 + ty * 4 + i;
        if (row < NQ) {
            #pragma unroll
            for (int j = 0; j < 4; j++) {
                int e = e0 + tx * 4 + j;
                g_dist[row * NM + e] = g_e2[e] - 2.f * acc[i][j];
            }
        }
    }
}

// ---------------- argmin + quantize + straight-through + loss + counts ----------------
__global__ __launch_bounds__(256)
void vq_k(const float* __restrict__ emb, float* __restrict__ out_q)
{
    const int warp = threadIdx.x >> 5;
    const int lane = threadIdx.x & 31;
    const int row = blockIdx.x * 8 + warp;     // 2044 * 8 = 16352 exact
    const float* dr = g_dist + row * NM;

    float best = 3.4e38f; int bi = NM;
    #pragma unroll
    for (int i = 0; i < 16; i++) {
        int e = i * 32 + lane;
        float v = dr[e];
        if (v < best) { best = v; bi = e; }
    }
    #pragma unroll
    for (int off = 16; off > 0; off >>= 1) {
        float ob = __shfl_down_sync(0xffffffffu, best, off);
        int   oi = __shfl_down_sync(0xffffffffu, bi,   off);
        if (ob < best || (ob == best && oi < bi)) { best = ob; bi = oi; }
    }
    bi = __shfl_sync(0xffffffffu, bi, 0);

    const float* zr = g_z + row * ND;
    const float* er = emb + bi * ND;
    float lsum = 0.f;
    #pragma unroll
    for (int d0 = 0; d0 < ND; d0 += 32) {
        int d = d0 + lane;
        float zv = zr[d], qv = er[d];
        out_q[row * ND + d] = zv + (qv - zv);   // straight-through (reference order)
        float df = zv - qv;
        lsum += df * df;
    }
    #pragma unroll
    for (int off = 16; off > 0; off >>= 1)
        lsum += __shfl_down_sync(0xffffffffu, lsum, off);
    if (lane == 0) {
        atomicAdd(&g_loss[0], lsum);
        atomicAdd(&g_counts[bi], 1);
    }
}

__global__ void finalize_k(float* __restrict__ out)
{
    __shared__ float sh[NM];
    int tid = threadIdx.x;
    float p = (float)g_counts[tid] / (float)NQ;
    sh[tid] = -p * logf(p + 1e-10f);
    __syncthreads();
    for (int s = NM / 2; s > 0; s >>= 1) {
        if (tid < s) sh[tid] += sh[tid + s];
        __syncthreads();
    }
    if (tid == 0) {
        out[NQE]     = 0.25f * g_loss[0] / (float)NQE;   // loss
        out[NQE + 1] = expf(sh[0]);                      // perplexity
    }
}

// ---------------- launcher ----------------
extern "C" void kernel_launch(void* const* d_in, const int* in_sizes, int n_in,
                              void* d_out, int out_size)
{
    const float* mels = (const float*)d_in[0];
    const float* w1   = (const float*)d_in[1];
    const float* w2   = (const float*)d_in[2];
    const float* w3   = (const float*)d_in[3];
    const float* w4   = (const float*)d_in[4];
    const float* w5   = (const float*)d_in[5];
    const float* w6   = (const float*)d_in[6];
    const float* b6   = (const float*)d_in[7];
    const float* bng  = (const float*)d_in[8];
    const float* bnb  = (const float*)d_in[9];
    const float* bnm  = (const float*)d_in[10];
    const float* bnv  = (const float*)d_in[11];
    const float* emb  = (const float*)d_in[12];
    float* out = (float*)d_out;

    float *bufA, *bufB, *w1T, *w2T, *w3T, *w4T, *w5T, *zbuf, *bnInv, *bnBeta;
    cudaGetSymbolAddress((void**)&bufA, g_bufA);
    cudaGetSymbolAddress((void**)&bufB, g_bufB);
    cudaGetSymbolAddress((void**)&w1T,  g_w1T);
    cudaGetSymbolAddress((void**)&w2T,  g_w2T);
    cudaGetSymbolAddress((void**)&w3T,  g_w3T);
    cudaGetSymbolAddress((void**)&w4T,  g_w4T);
    cudaGetSymbolAddress((void**)&w5T,  g_w5T);
    cudaGetSymbolAddress((void**)&zbuf, g_z);
    cudaGetSymbolAddress((void**)&bnInv,  g_bnInv);
    cudaGetSymbolAddress((void**)&bnBeta, g_bnBeta);

    zero_k<<<1, 576>>>();
    bnprep_k<<<(5 * NC + 255) / 256, 256>>>(bng, bnb, bnm, bnv);
    transpose_w_k<<<(NC * CIN0 * 3 + 255) / 256, 256>>>(w1, w1T, NC, CIN0 * 3);
    transpose_w_k<<<(NC * NC * 3 + 255) / 256, 256>>>(w2, w2T, NC, NC * 3);
    transpose_w_k<<<(NC * NC * 4 + 255) / 256, 256>>>(w3, w3T, NC, NC * 4);
    transpose_w_k<<<(NC * NC * 3 + 255) / 256, 256>>>(w4, w4T, NC, NC * 3);
    transpose_w_k<<<(NC * NC * 3 + 255) / 256, 256>>>(w5, w5T, NC, NC * 3);
    e2_k<<<2, 256>>>(emb);

    dim3 blk(16, 16);
    // conv1: [32,80,1024] -> [32,768,1022]
    conv_bn_relu_k<3, 1, 0, CIN0, T0, T1><<<dim3((NB * T1) / 64, NC / 64), blk>>>(
        mels, w1T, bnInv + 0 * NC, bnBeta + 0 * NC, bufA);
    // conv2: -> [32,768,1022]
    conv_bn_relu_k<3, 1, 1, NC, T1, T1><<<dim3((NB * T1) / 64, NC / 64), blk>>>(
        bufA, w2T, bnInv + 1 * NC, bnBeta + 1 * NC, bufB);
    // conv3 (stride 2): -> [32,768,511]
    conv_bn_relu_k<4, 2, 1, NC, T1, T2><<<dim3((NB * T2 + 63) / 64, NC / 64), blk>>>(
        bufB, w3T, bnInv + 2 * NC, bnBeta + 2 * NC, bufA);
    // conv4
    conv_bn_relu_k<3, 1, 1, NC, T2, T2><<<dim3((NB * T2 + 63) / 64, NC / 64), blk>>>(
        bufA, w4T, bnInv + 3 * NC, bnBeta + 3 * NC, bufB);
    // conv5
    conv_bn_relu_k<3, 1, 1, NC, T2, T2><<<dim3((NB * T2 + 63) / 64, NC / 64), blk>>>(
        bufB, w5T, bnInv + 4 * NC, bnBeta + 4 * NC, bufA);
    // 1x1 projection + transpose -> z [B, T', D]
    conv6_k<<<dim3((T2 + 63) / 64, NB), blk>>>(bufA, w6, b6, zbuf);
    // VQ
    dist_k<<<dim3((NQ + 63) / 64, NM / 64), blk>>>(emb);
    vq_k<<<NQ / 8, 256>>>(emb, out);
    finalize_k<<<1, NM>>>(out);
}